// round 10
// baseline (speedup 1.0000x reference)
#include <cuda_runtime.h>
#include <math.h>

#define NG 1024
#define IMG_H 128
#define IMG_W 128
#define FXc 128.0f
#define FYc 128.0f
#define CLIPX 0.65f   // 1.3 * TANX
#define CLIPY 0.65f   // 1.3 * TANY
#define NT 512        // block threads
#define NPIX 64       // 8x8 tile
#define NSEG 8        // depth segments per pixel
#define SCH 512       // staging chunk (== NT)
#define NBLK 128      // grid size (<=148 SMs: co-resident, spin-barrier safe)
#define TILES_PER_BLK 2

// ---------------- device scratch (no allocations allowed) ----------------
__device__ float4 u_geo[NG];    // unsorted: x, y, conA, conB
__device__ float4 u_cull[NG];   // unsorted: rx, ry, depth, 0
__device__ float4 u_col[NG];    // unsorted: conC, r, g, b
__device__ float2 u_op2[NG];    // unsorted: opacity, pth
__device__ float4 sg_geo[NG];   // SORTED by depth: x, y, conA, conB
__device__ float2 sg_cul[NG];   // SORTED: rx, ry
__device__ float4 sg_col[NG];   // SORTED: conC, r, g, b
__device__ float2 sg_op2[NG];   // SORTED: opacity, pth
__device__ unsigned g_gbar;     // generation spin barrier (monotone, never reset)

__device__ __forceinline__ void grid_barrier(int tid)
{
    __threadfence();
    __syncthreads();
    if (tid == 0) {
        unsigned arrival = atomicAdd(&g_gbar, 1u) + 1u;
        unsigned target = ((arrival + (NBLK-1u)) / NBLK) * NBLK;  // ceil to mult of NBLK
        while (atomicAdd(&g_gbar, 0u) < target) { }
    }
    __syncthreads();
    __threadfence();
}

// ---------------- fused persistent kernel ----------------
__global__ __launch_bounds__(NT)
void gauss_kernel(const float* __restrict__ means3D,
                  const float* __restrict__ opacities,
                  const float* __restrict__ shs,
                  const float* __restrict__ scales,
                  const float* __restrict__ rotations,
                  const float* __restrict__ vm,
                  const float* __restrict__ pm,
                  const float* __restrict__ campos,
                  const float* __restrict__ bg,
                  float* __restrict__ out)
{
    __shared__ unsigned long long skey[NG];   // phase 2: all keys ; phase 3: unused
    __shared__ int    sidx[NG];               // phase 3: sorted survivor positions
    __shared__ float4 cgeo[SCH];
    __shared__ float4 ccol[SCH];
    __shared__ float2 cop2[SCH];
    __shared__ float4 mseg[NSEG][NPIX];
    __shared__ int    wcnt[NT/32];

    int tid = threadIdx.x;
    int blk = blockIdx.x;
    int lane = tid & 31;
    int wid  = tid >> 5;

    // ================= phase 1: preprocess (blocks 0..15, threads 0..63) ============
    if (blk < 16 && tid < 64) {
        int i = blk*64 + tid;

        float mx = means3D[3*i+0], my = means3D[3*i+1], mz = means3D[3*i+2];

        float pv0 = mx*vm[0] + my*vm[4] + mz*vm[8]  + vm[12];
        float pv1 = mx*vm[1] + my*vm[5] + mz*vm[9]  + vm[13];
        float pv2 = mx*vm[2] + my*vm[6] + mz*vm[10] + vm[14];
        float depth = pv2;

        float ph0 = mx*pm[0] + my*pm[4] + mz*pm[8]  + pm[12];
        float ph1 = mx*pm[1] + my*pm[5] + mz*pm[9]  + pm[13];
        float ph3 = mx*pm[3] + my*pm[7] + mz*pm[11] + pm[15];
        float invw = 1.0f / (ph3 + 1e-7f);
        float ppx = ph0 * invw, ppy = ph1 * invw;

        float4 q = reinterpret_cast<const float4*>(rotations)[i];
        float qr = q.x, qx = q.y, qy = q.z, qz = q.w;
        float qn = rsqrtf(qr*qr + qx*qx + qy*qy + qz*qz);
        qr *= qn; qx *= qn; qy *= qn; qz *= qn;
        float R00 = 1.f - 2.f*(qy*qy + qz*qz), R01 = 2.f*(qx*qy - qr*qz), R02 = 2.f*(qx*qz + qr*qy);
        float R10 = 2.f*(qx*qy + qr*qz), R11 = 1.f - 2.f*(qx*qx + qz*qz), R12 = 2.f*(qy*qz - qr*qx);
        float R20 = 2.f*(qx*qz - qr*qy), R21 = 2.f*(qy*qz + qr*qx), R22 = 1.f - 2.f*(qx*qx + qy*qy);

        float s0 = scales[3*i+0], s1 = scales[3*i+1], s2 = scales[3*i+2];
        float M00 = R00*s0, M01 = R01*s1, M02 = R02*s2;
        float M10 = R10*s0, M11 = R11*s1, M12 = R12*s2;
        float M20 = R20*s0, M21 = R21*s1, M22 = R22*s2;

        float S00 = M00*M00 + M01*M01 + M02*M02;
        float S01 = M00*M10 + M01*M11 + M02*M12;
        float S02 = M00*M20 + M01*M21 + M02*M22;
        float S11 = M10*M10 + M11*M11 + M12*M12;
        float S12 = M10*M20 + M11*M21 + M12*M22;
        float S22 = M20*M20 + M21*M21 + M22*M22;

        float tz = (depth > 0.2f) ? depth : 1.0f;
        float invz = 1.0f / tz;
        float txtz = fminf(fmaxf(pv0*invz, -CLIPX), CLIPX) * tz;
        float tytz = fminf(fmaxf(pv1*invz, -CLIPY), CLIPY) * tz;
        float J00 = FXc*invz, J02 = -FXc*txtz*invz*invz;
        float J11 = FYc*invz, J12 = -FYc*tytz*invz*invz;

        float t00 = J00*vm[0]  + J02*vm[2];
        float t01 = J00*vm[4]  + J02*vm[6];
        float t02 = J00*vm[8]  + J02*vm[10];
        float t10 = J11*vm[1]  + J12*vm[2];
        float t11 = J11*vm[5]  + J12*vm[6];
        float t12 = J11*vm[9]  + J12*vm[10];

        float a = t00*t00*S00 + t01*t01*S11 + t02*t02*S22
                + 2.f*(t00*t01*S01 + t00*t02*S02 + t01*t02*S12) + 0.3f;
        float c = t10*t10*S00 + t11*t11*S11 + t12*t12*S22
                + 2.f*(t10*t11*S01 + t10*t12*S02 + t11*t12*S12) + 0.3f;
        float b = t00*t10*S00 + t01*t11*S11 + t02*t12*S22
                + (t00*t11 + t01*t10)*S01 + (t00*t12 + t02*t10)*S02 + (t01*t12 + t02*t11)*S12;

        float det = a*c - b*b;
        bool valid = (depth > 0.2f) && (det > 0.0f);
        float inv_det = 1.0f / ((det > 0.0f) ? det : 1.0f);
        float conA = c*inv_det, conB = -b*inv_det, conC = a*inv_det;

        float mid = 0.5f*(a + c);
        float lam1 = mid + sqrtf(fmaxf(0.1f, mid*mid - det));
        float radii = valid ? ceilf(3.0f * sqrtf(lam1)) : 0.0f;

        float xyx = ((ppx + 1.0f)*(float)IMG_W - 1.0f)*0.5f;
        float xyy = ((ppy + 1.0f)*(float)IMG_H - 1.0f)*0.5f;

        float dx = mx - campos[0], dy = my - campos[1], dz = mz - campos[2];
        float dn = rsqrtf(dx*dx + dy*dy + dz*dz);
        float x = dx*dn, y = dy*dn, z = dz*dn;
        float xx = x*x, yy = y*y, zz = z*z;
        float xy = x*y, yz = y*z, xz = x*z;

        const float C0f = 0.28209479177387814f;
        const float C1f = 0.4886025119029199f;
        float basis[16];
        basis[0]  = C0f;
        basis[1]  = -C1f*y;
        basis[2]  =  C1f*z;
        basis[3]  = -C1f*x;
        basis[4]  =  1.0925484305920792f * xy;
        basis[5]  = -1.0925484305920792f * yz;
        basis[6]  =  0.31539156525252005f * (2.f*zz - xx - yy);
        basis[7]  = -1.0925484305920792f * xz;
        basis[8]  =  0.5462742152960396f * (xx - yy);
        basis[9]  = -0.5900435899266435f * y * (3.f*xx - yy);
        basis[10] =  2.890611442640554f  * xy * z;
        basis[11] = -0.4570457994644658f * y * (4.f*zz - xx - yy);
        basis[12] =  0.3731763325901154f * z * (2.f*zz - 3.f*xx - 3.f*yy);
        basis[13] = -0.4570457994644658f * x * (4.f*zz - xx - yy);
        basis[14] =  1.445305721320277f  * z * (xx - yy);
        basis[15] = -0.5900435899266435f * x * (xx - 3.f*yy);

        float shv[48];
        {
            const float4* sh4 = reinterpret_cast<const float4*>(shs + i*48);
            #pragma unroll
            for (int k2 = 0; k2 < 12; k2++) {
                float4 v4 = sh4[k2];
                shv[4*k2+0] = v4.x; shv[4*k2+1] = v4.y; shv[4*k2+2] = v4.z; shv[4*k2+3] = v4.w;
            }
        }
        float cr = 0.f, cg = 0.f, cb = 0.f;
        #pragma unroll
        for (int k2 = 0; k2 < 16; k2++) {
            cr += basis[k2]*shv[3*k2+0];
            cg += basis[k2]*shv[3*k2+1];
            cb += basis[k2]*shv[3*k2+2];
        }
        cr = fmaxf(cr + 0.5f, 0.f);
        cg = fmaxf(cg + 0.5f, 0.f);
        cb = fmaxf(cb + 0.5f, 0.f);

        float op = opacities[i];
        float mpth = logf(255.0f * op);

        float rxe, rye;
        if (valid && mpth > 0.0f) {
            rxe = sqrtf(2.0f*mpth*a);
            rye = sqrtf(2.0f*mpth*c);
        } else {
            rxe = -1.0f; rye = -1.0f;
        }

        u_geo[i]  = make_float4(xyx, xyy, conA, conB);
        u_cull[i] = make_float4(rxe, rye, valid ? depth : INFINITY, 0.0f);
        u_col[i]  = make_float4(conC, cr, cg, cb);
        u_op2[i]  = make_float2(op, -mpth);

        out[IMG_H*IMG_W*3 + i] = radii;
    }

    grid_barrier(tid);

    // ================= phase 2: parallel global rank-sort (blocks 0..31) ============
    if (blk < 32) {
        // load all packed keys into shared
        #pragma unroll
        for (int rep = 0; rep < NG/NT; rep++) {
            int j = tid + rep*NT;
            float4 cu = __ldcg(reinterpret_cast<const float4*>(&u_cull[j]));
            skey[j] = ((unsigned long long)__float_as_uint(cu.z) << 32) | (unsigned)j;
        }
        __syncthreads();

        // 32 gaussians per block; 16 threads per gaussian, 64 keys per thread
        int g = blk*32 + (tid >> 4);
        int slice = tid & 15;
        unsigned long long mykey = skey[g];
        int cnt = 0;
        int j0 = slice*64;
        #pragma unroll 8
        for (int j = j0; j < j0+64; j++)
            cnt += (skey[j] < mykey) ? 1 : 0;
        // reduce over 16 lanes (same gaussian)
        #pragma unroll
        for (int off = 8; off >= 1; off >>= 1)
            cnt += __shfl_down_sync(0xffffffffu, cnt, off, 16);
        if (slice == 0) {
            int rank = cnt;   // exact stable argsort position
            sg_geo[rank] = __ldcg(reinterpret_cast<const float4*>(&u_geo[g]));
            float4 cu = __ldcg(reinterpret_cast<const float4*>(&u_cull[g]));
            sg_cul[rank] = make_float2(cu.x, cu.y);
            sg_col[rank] = __ldcg(reinterpret_cast<const float4*>(&u_col[g]));
            sg_op2[rank] = __ldcg(reinterpret_cast<const float2*>(&u_op2[g]));
        }
    }

    grid_barrier(tid);

    // ================= phase 3: raster 2 tiles per block (sorted input, no sort) ====
    int pix  = tid & 63;
    int seg  = tid >> 6;
    int tx = pix & 7, ty = pix >> 3;
    float bgr = bg[0], bgg = bg[1], bgb = bg[2];

    for (int trep = 0; trep < TILES_PER_BLK; trep++) {
        int tile = blk + trep*NBLK;                 // 0..255
        int tbx = tile & 15, tby = tile >> 4;       // 16x16 tile grid
        float fx = (float)(tbx*8 + tx);
        float fy = (float)(tby*8 + ty);
        float tminx = (float)(tbx*8), tmaxx = tminx + 7.0f;
        float tminy = (float)(tby*8), tmaxy = tminy + 7.0f;

        // ---- cull sorted gaussians, ORDER-PRESERVING compaction of indices ----
        int cbase = 0;
        #pragma unroll
        for (int rep = 0; rep < NG/NT; rep++) {
            int i = tid + rep*NT;
            float4 ge = __ldcg(reinterpret_cast<const float4*>(&sg_geo[i]));
            float2 cu = __ldcg(reinterpret_cast<const float2*>(&sg_cul[i]));
            float cx = fminf(fmaxf(ge.x, tminx), tmaxx);
            float cy = fminf(fmaxf(ge.y, tminy), tmaxy);
            bool keep = (fabsf(ge.x - cx) <= cu.x) && (fabsf(ge.y - cy) <= cu.y);
            unsigned m = __ballot_sync(0xffffffffu, keep);
            if (lane == 0) wcnt[wid] = __popc(m);
            __syncthreads();
            int off = cbase, tot = 0;
            #pragma unroll
            for (int w = 0; w < NT/32; w++) {
                int c8 = wcnt[w];
                if (w < wid) off += c8;
                tot += c8;
            }
            if (keep) sidx[off + __popc(m & ((1u << lane) - 1u))] = i;
            cbase += tot;
            __syncthreads();
        }
        int cnt = cbase;

        float Trun = 1.0f;
        float cr = 0.f, cg = 0.f, cb = 0.f;
        bool done = false;

        for (int c0 = 0; c0 < cnt; c0 += SCH) {
            int j2 = c0 + tid;
            if (j2 < cnt) {
                int idx = sidx[j2];
                cgeo[tid] = __ldcg(reinterpret_cast<const float4*>(&sg_geo[idx]));
                ccol[tid] = __ldcg(reinterpret_cast<const float4*>(&sg_col[idx]));
                cop2[tid] = __ldcg(reinterpret_cast<const float2*>(&sg_op2[idx]));
            }
            __syncthreads();
            int ccnt = min(SCH, cnt - c0);

            float scr = 0.f, scg = 0.f, scb = 0.f, sT = 1.0f;
            if (!done) {
                int js = (ccnt * seg) / NSEG;
                int je = (ccnt * (seg+1)) / NSEG;
                for (int j = js; j < je; j++) {
                    float4 g4 = cgeo[j];
                    float4 col = ccol[j];
                    float dx = g4.x - fx;
                    float dy = g4.y - fy;
                    float power = -0.5f*(g4.z*dx*dx + col.x*dy*dy) - g4.w*dx*dy;
                    float2 o2 = cop2[j];
                    if (power > 0.0f || power < o2.y) continue;
                    float alpha = fminf(0.99f, o2.x * __expf(power));
                    if (alpha < (1.0f/255.0f)) continue;
                    float w = sT * alpha;
                    scr += w * col.y;
                    scg += w * col.z;
                    scb += w * col.w;
                    sT  *= (1.0f - alpha);
                }
            }
            mseg[seg][pix] = make_float4(scr, scg, scb, sT);
            __syncthreads();

            if (!done) {
                int s;
                #pragma unroll
                for (s = 0; s < NSEG; s++) {
                    float4 ms = mseg[s][pix];
                    if (Trun * ms.w >= 1e-4f) {
                        cr += Trun * ms.x;
                        cg += Trun * ms.y;
                        cb += Trun * ms.z;
                        Trun *= ms.w;
                    } else break;
                }
                if (s < NSEG) {
                    // 1e-4 crossing inside segment s: exact serial re-walk
                    int js = (ccnt * s) / NSEG;
                    int je = (ccnt * (s+1)) / NSEG;
                    for (int j = js; j < je; j++) {
                        float4 g4 = cgeo[j];
                        float4 col = ccol[j];
                        float dx = g4.x - fx;
                        float dy = g4.y - fy;
                        float power = -0.5f*(g4.z*dx*dx + col.x*dy*dy) - g4.w*dx*dy;
                        float2 o2 = cop2[j];
                        if (power > 0.0f || power < o2.y) continue;
                        float alpha = fminf(0.99f, o2.x * __expf(power));
                        if (alpha < (1.0f/255.0f)) continue;
                        float Tnew = Trun * (1.0f - alpha);
                        if (Tnew < 1e-4f) break;
                        float w = Trun * alpha;
                        cr += w * col.y;
                        cg += w * col.z;
                        cb += w * col.w;
                        Trun = Tnew;
                    }
                    done = true;
                }
            }
            if (__syncthreads_count(done ? 1 : 0) == NT) break;
        }

        if (seg == 0) {
            int pxi = (tby*8 + ty)*IMG_W + (tbx*8 + tx);
            out[0*IMG_H*IMG_W + pxi] = cr + bgr*Trun;
            out[1*IMG_H*IMG_W + pxi] = cg + bgg*Trun;
            out[2*IMG_H*IMG_W + pxi] = cb + bgb*Trun;
        }
        __syncthreads();
    }
}

// ---------------- launch ----------------
extern "C" void kernel_launch(void* const* d_in, const int* in_sizes, int n_in,
                              void* d_out, int out_size)
{
    const float* means3D   = (const float*)d_in[0];
    // d_in[1] = means2D (unused)
    const float* opacities = (const float*)d_in[2];
    const float* shs       = (const float*)d_in[3];
    const float* scales    = (const float*)d_in[4];
    const float* rotations = (const float*)d_in[5];
    const float* viewm     = (const float*)d_in[6];
    const float* projm     = (const float*)d_in[7];
    const float* campos    = (const float*)d_in[8];
    const float* bg        = (const float*)d_in[9];
    float* out = (float*)d_out;

    gauss_kernel<<<NBLK, NT>>>(means3D, opacities, shs, scales, rotations,
                               viewm, projm, campos, bg, out);
}

// round 11
// speedup vs baseline: 1.8020x; 1.8020x over previous
#include <cuda_runtime.h>
#include <math.h>

#define NG 1024
#define IMG_H 128
#define IMG_W 128
#define FXc 128.0f
#define FYc 128.0f
#define CLIPX 0.65f   // 1.3 * TANX
#define CLIPY 0.65f   // 1.3 * TANY
#define NT 512        // block threads
#define NPIX 128      // 16x8 region
#define NSEG 4        // depth segments per pixel
#define SCH 512       // staging chunk (== NT)
#define NBLK 128      // grid size (<=148 SMs: co-resident, spin-barrier safe)
#define KMAX 0xFFFFFFFFFFFFFFFFull

// ---------------- device scratch (no allocations allowed) ----------------
__device__ float4 u_geo[NG];    // x, y, conA, conB
__device__ float4 u_cull[NG];   // rx, ry, depth(INF if invalid), 0
__device__ float4 u_col[NG];    // conC, r, g, b
__device__ float2 u_op2[NG];    // opacity, pth
__device__ unsigned g_gbar;     // generation spin barrier (monotone, never reset)

// ---------------- u64 warp bitonic stage ----------------
__device__ __forceinline__ void wstage64(unsigned long long& kk, int t, int stride, bool asc)
{
    unsigned long long ko = __shfl_xor_sync(0xffffffffu, kk, stride);
    bool lower = ((t & stride) == 0);
    bool take = asc ? (lower ? (kk > ko) : (kk < ko))
                    : (lower ? (kk < ko) : (kk > ko));
    if (take) kk = ko;
}

// ---------------- fused persistent kernel ----------------
__global__ __launch_bounds__(NT)
void gauss_kernel(const float* __restrict__ means3D,
                  const float* __restrict__ opacities,
                  const float* __restrict__ shs,
                  const float* __restrict__ scales,
                  const float* __restrict__ rotations,
                  const float* __restrict__ vm,
                  const float* __restrict__ pm,
                  const float* __restrict__ campos,
                  const float* __restrict__ bg,
                  float* __restrict__ out)
{
    __shared__ unsigned long long skey[NG];
    __shared__ float4 cgeo[SCH];
    __shared__ float4 ccol[SCH];
    __shared__ float2 cop2[SCH];
    __shared__ float4 mseg[NSEG][NPIX];
    __shared__ int    scnt;

    int tid = threadIdx.x;
    int blk = blockIdx.x;
    int lane = tid & 31;

    // ================= phase 1: preprocess (blocks 0..15, threads 0..63) ============
    if (blk < 16 && tid < 64) {
        int i = blk*64 + tid;

        float mx = means3D[3*i+0], my = means3D[3*i+1], mz = means3D[3*i+2];

        float pv0 = mx*vm[0] + my*vm[4] + mz*vm[8]  + vm[12];
        float pv1 = mx*vm[1] + my*vm[5] + mz*vm[9]  + vm[13];
        float pv2 = mx*vm[2] + my*vm[6] + mz*vm[10] + vm[14];
        float depth = pv2;

        float ph0 = mx*pm[0] + my*pm[4] + mz*pm[8]  + pm[12];
        float ph1 = mx*pm[1] + my*pm[5] + mz*pm[9]  + pm[13];
        float ph3 = mx*pm[3] + my*pm[7] + mz*pm[11] + pm[15];
        float invw = 1.0f / (ph3 + 1e-7f);
        float ppx = ph0 * invw, ppy = ph1 * invw;

        float4 q = reinterpret_cast<const float4*>(rotations)[i];
        float qr = q.x, qx = q.y, qy = q.z, qz = q.w;
        float qn = rsqrtf(qr*qr + qx*qx + qy*qy + qz*qz);
        qr *= qn; qx *= qn; qy *= qn; qz *= qn;
        float R00 = 1.f - 2.f*(qy*qy + qz*qz), R01 = 2.f*(qx*qy - qr*qz), R02 = 2.f*(qx*qz + qr*qy);
        float R10 = 2.f*(qx*qy + qr*qz), R11 = 1.f - 2.f*(qx*qx + qz*qz), R12 = 2.f*(qy*qz - qr*qx);
        float R20 = 2.f*(qx*qz - qr*qy), R21 = 2.f*(qy*qz + qr*qx), R22 = 1.f - 2.f*(qx*qx + qy*qy);

        float s0 = scales[3*i+0], s1 = scales[3*i+1], s2 = scales[3*i+2];
        float M00 = R00*s0, M01 = R01*s1, M02 = R02*s2;
        float M10 = R10*s0, M11 = R11*s1, M12 = R12*s2;
        float M20 = R20*s0, M21 = R21*s1, M22 = R22*s2;

        float S00 = M00*M00 + M01*M01 + M02*M02;
        float S01 = M00*M10 + M01*M11 + M02*M12;
        float S02 = M00*M20 + M01*M21 + M02*M22;
        float S11 = M10*M10 + M11*M11 + M12*M12;
        float S12 = M10*M20 + M11*M21 + M12*M22;
        float S22 = M20*M20 + M21*M21 + M22*M22;

        float tz = (depth > 0.2f) ? depth : 1.0f;
        float invz = 1.0f / tz;
        float txtz = fminf(fmaxf(pv0*invz, -CLIPX), CLIPX) * tz;
        float tytz = fminf(fmaxf(pv1*invz, -CLIPY), CLIPY) * tz;
        float J00 = FXc*invz, J02 = -FXc*txtz*invz*invz;
        float J11 = FYc*invz, J12 = -FYc*tytz*invz*invz;

        float t00 = J00*vm[0]  + J02*vm[2];
        float t01 = J00*vm[4]  + J02*vm[6];
        float t02 = J00*vm[8]  + J02*vm[10];
        float t10 = J11*vm[1]  + J12*vm[2];
        float t11 = J11*vm[5]  + J12*vm[6];
        float t12 = J11*vm[9]  + J12*vm[10];

        float a = t00*t00*S00 + t01*t01*S11 + t02*t02*S22
                + 2.f*(t00*t01*S01 + t00*t02*S02 + t01*t02*S12) + 0.3f;
        float c = t10*t10*S00 + t11*t11*S11 + t12*t12*S22
                + 2.f*(t10*t11*S01 + t10*t12*S02 + t11*t12*S12) + 0.3f;
        float b = t00*t10*S00 + t01*t11*S11 + t02*t12*S22
                + (t00*t11 + t01*t10)*S01 + (t00*t12 + t02*t10)*S02 + (t01*t12 + t02*t11)*S12;

        float det = a*c - b*b;
        bool valid = (depth > 0.2f) && (det > 0.0f);
        float inv_det = 1.0f / ((det > 0.0f) ? det : 1.0f);
        float conA = c*inv_det, conB = -b*inv_det, conC = a*inv_det;

        float mid = 0.5f*(a + c);
        float lam1 = mid + sqrtf(fmaxf(0.1f, mid*mid - det));
        float radii = valid ? ceilf(3.0f * sqrtf(lam1)) : 0.0f;

        float xyx = ((ppx + 1.0f)*(float)IMG_W - 1.0f)*0.5f;
        float xyy = ((ppy + 1.0f)*(float)IMG_H - 1.0f)*0.5f;

        float dx = mx - campos[0], dy = my - campos[1], dz = mz - campos[2];
        float dn = rsqrtf(dx*dx + dy*dy + dz*dz);
        float x = dx*dn, y = dy*dn, z = dz*dn;
        float xx = x*x, yy = y*y, zz = z*z;
        float xy = x*y, yz = y*z, xz = x*z;

        const float C0f = 0.28209479177387814f;
        const float C1f = 0.4886025119029199f;
        float basis[16];
        basis[0]  = C0f;
        basis[1]  = -C1f*y;
        basis[2]  =  C1f*z;
        basis[3]  = -C1f*x;
        basis[4]  =  1.0925484305920792f * xy;
        basis[5]  = -1.0925484305920792f * yz;
        basis[6]  =  0.31539156525252005f * (2.f*zz - xx - yy);
        basis[7]  = -1.0925484305920792f * xz;
        basis[8]  =  0.5462742152960396f * (xx - yy);
        basis[9]  = -0.5900435899266435f * y * (3.f*xx - yy);
        basis[10] =  2.890611442640554f  * xy * z;
        basis[11] = -0.4570457994644658f * y * (4.f*zz - xx - yy);
        basis[12] =  0.3731763325901154f * z * (2.f*zz - 3.f*xx - 3.f*yy);
        basis[13] = -0.4570457994644658f * x * (4.f*zz - xx - yy);
        basis[14] =  1.445305721320277f  * z * (xx - yy);
        basis[15] = -0.5900435899266435f * x * (xx - 3.f*yy);

        float shv[48];
        {
            const float4* sh4 = reinterpret_cast<const float4*>(shs + i*48);
            #pragma unroll
            for (int k2 = 0; k2 < 12; k2++) {
                float4 v4 = sh4[k2];
                shv[4*k2+0] = v4.x; shv[4*k2+1] = v4.y; shv[4*k2+2] = v4.z; shv[4*k2+3] = v4.w;
            }
        }
        float cr = 0.f, cg = 0.f, cb = 0.f;
        #pragma unroll
        for (int k2 = 0; k2 < 16; k2++) {
            cr += basis[k2]*shv[3*k2+0];
            cg += basis[k2]*shv[3*k2+1];
            cb += basis[k2]*shv[3*k2+2];
        }
        cr = fmaxf(cr + 0.5f, 0.f);
        cg = fmaxf(cg + 0.5f, 0.f);
        cb = fmaxf(cb + 0.5f, 0.f);

        float op = opacities[i];
        float mpth = logf(255.0f * op);

        float rxe, rye;
        if (valid && mpth > 0.0f) {
            rxe = sqrtf(2.0f*mpth*a);
            rye = sqrtf(2.0f*mpth*c);
        } else {
            rxe = -1.0f; rye = -1.0f;
        }

        u_geo[i]  = make_float4(xyx, xyy, conA, conB);
        u_cull[i] = make_float4(rxe, rye, valid ? depth : INFINITY, 0.0f);
        u_col[i]  = make_float4(conC, cr, cg, cb);
        u_op2[i]  = make_float2(op, -mpth);

        out[IMG_H*IMG_W*3 + i] = radii;
    }

    // ============ grid-wide spin barrier: atomic arrive, VOLATILE READ poll ==========
    __threadfence();
    __syncthreads();
    if (tid == 0) {
        unsigned arrival = atomicAdd(&g_gbar, 1u) + 1u;
        unsigned target = ((arrival + (NBLK-1u)) / NBLK) * NBLK;   // ceil to mult of NBLK
        volatile unsigned* gb = &g_gbar;
        while (*gb < target) { }
    }
    __syncthreads();
    __threadfence();

    // ================= phase 2: raster one 16x8 region per block =====================
    int pix  = tid & (NPIX-1);          // 0..127
    int seg  = tid >> 7;                // 0..3
    int tx = pix & 15, ty = pix >> 4;   // 16 wide, 8 tall
    int rx0 = (blk & 7) * 16;
    int ry0 = (blk >> 3) * 8;
    float fx = (float)(rx0 + tx);
    float fy = (float)(ry0 + ty);
    float tminx = (float)rx0, tmaxx = tminx + 15.0f;
    float tminy = (float)ry0, tmaxy = tminy + 7.0f;
    float bgr = bg[0], bgg = bg[1], bgb = bg[2];

    if (tid == 0) scnt = 0;
    __syncthreads();

    // ---- cull all NG gaussians (2 per thread), warp-compact survivor keys ----
    #pragma unroll
    for (int rep = 0; rep < NG/NT; rep++) {
        int i = tid + rep*NT;
        float4 ge = __ldcg(reinterpret_cast<const float4*>(&u_geo[i]));
        float4 cu = __ldcg(reinterpret_cast<const float4*>(&u_cull[i]));
        float cx = fminf(fmaxf(ge.x, tminx), tmaxx);
        float cy = fminf(fmaxf(ge.y, tminy), tmaxy);
        bool keep = (fabsf(ge.x - cx) <= cu.x) && (fabsf(ge.y - cy) <= cu.y);
        unsigned m = __ballot_sync(0xffffffffu, keep);
        int base = 0;
        if (lane == 0 && m) base = atomicAdd(&scnt, __popc(m));
        base = __shfl_sync(0xffffffffu, base, 0);
        if (keep) {
            int pos = base + __popc(m & ((1u << lane) - 1u));
            skey[pos] = ((unsigned long long)__float_as_uint(cu.z) << 32) | (unsigned)i;
        }
    }
    __syncthreads();
    int cnt = scnt;

    float Trun = 1.0f;
    float cr = 0.f, cg = 0.f, cb = 0.f;

    if (cnt > 0) {
        if (cnt <= NT) {
            // ---- hybrid register/shuffle bitonic (one element per thread) ----
            int P = 32;
            while (P < cnt) P <<= 1;
            unsigned long long kk = (tid < cnt) ? skey[tid] : KMAX;
            #pragma unroll
            for (int size = 2; size <= 32; size <<= 1) {
                bool asc = ((tid & size) == 0);
                #pragma unroll
                for (int stride = size >> 1; stride >= 1; stride >>= 1)
                    wstage64(kk, tid, stride, asc);
            }
            skey[tid] = kk;
            __syncthreads();
            for (int size = 64; size <= P; size <<= 1) {
                bool asc = ((tid & size) == 0);
                for (int stride = size >> 1; stride >= 32; stride >>= 1) {
                    int j = tid ^ stride;
                    if (j > tid) {
                        unsigned long long a2 = skey[tid], b2 = skey[j];
                        if ((a2 > b2) == asc) { skey[tid] = b2; skey[j] = a2; }
                    }
                    __syncthreads();
                }
                kk = skey[tid];
                #pragma unroll
                for (int stride = 16; stride >= 1; stride >>= 1)
                    wstage64(kk, tid, stride, asc);
                skey[tid] = kk;
                __syncthreads();
            }
        } else {
            // ---- fallback: strided shared network (cnt up to NG) ----
            int P = 1;
            while (P < cnt) P <<= 1;
            for (int j = cnt + tid; j < P; j += NT) skey[j] = KMAX;
            __syncthreads();
            for (int size = 2; size <= P; size <<= 1) {
                for (int stride = size >> 1; stride >= 1; stride >>= 1) {
                    for (int j = tid; j < (P >> 1); j += NT) {
                        int lo = ((j / stride) * (stride << 1)) + (j % stride);
                        int hi = lo + stride;
                        bool asc = ((lo & size) == 0);
                        unsigned long long a2 = skey[lo], b2 = skey[hi];
                        if ((a2 > b2) == asc) { skey[lo] = b2; skey[hi] = a2; }
                    }
                    __syncthreads();
                }
            }
        }

        // ---- composite sorted survivors in chunks of SCH ----
        bool done = false;
        for (int c0 = 0; c0 < cnt; c0 += SCH) {
            int j2 = c0 + tid;
            if (j2 < cnt) {
                int idx = (int)(skey[j2] & 0xFFFFFu);
                cgeo[tid] = __ldcg(reinterpret_cast<const float4*>(&u_geo[idx]));
                ccol[tid] = __ldcg(reinterpret_cast<const float4*>(&u_col[idx]));
                cop2[tid] = __ldcg(reinterpret_cast<const float2*>(&u_op2[idx]));
            }
            __syncthreads();
            int ccnt = min(SCH, cnt - c0);

            float scr = 0.f, scg = 0.f, scb = 0.f, sT = 1.0f;
            if (!done) {
                int js = (ccnt * seg) / NSEG;
                int je = (ccnt * (seg+1)) / NSEG;
                for (int j = js; j < je; j++) {
                    float4 g4 = cgeo[j];
                    float4 col = ccol[j];
                    float dx = g4.x - fx;
                    float dy = g4.y - fy;
                    float power = -0.5f*(g4.z*dx*dx + col.x*dy*dy) - g4.w*dx*dy;
                    float2 o2 = cop2[j];
                    if (power > 0.0f || power < o2.y) continue;
                    float alpha = fminf(0.99f, o2.x * __expf(power));
                    if (alpha < (1.0f/255.0f)) continue;
                    float w = sT * alpha;
                    scr += w * col.y;
                    scg += w * col.z;
                    scb += w * col.w;
                    sT  *= (1.0f - alpha);
                }
            }
            mseg[seg][pix] = make_float4(scr, scg, scb, sT);
            __syncthreads();

            if (!done) {
                int s;
                #pragma unroll
                for (s = 0; s < NSEG; s++) {
                    float4 ms = mseg[s][pix];
                    if (Trun * ms.w >= 1e-4f) {
                        cr += Trun * ms.x;
                        cg += Trun * ms.y;
                        cb += Trun * ms.z;
                        Trun *= ms.w;
                    } else break;
                }
                if (s < NSEG) {
                    // 1e-4 crossing inside segment s: exact serial re-walk
                    int js = (ccnt * s) / NSEG;
                    int je = (ccnt * (s+1)) / NSEG;
                    for (int j = js; j < je; j++) {
                        float4 g4 = cgeo[j];
                        float4 col = ccol[j];
                        float dx = g4.x - fx;
                        float dy = g4.y - fy;
                        float power = -0.5f*(g4.z*dx*dx + col.x*dy*dy) - g4.w*dx*dy;
                        float2 o2 = cop2[j];
                        if (power > 0.0f || power < o2.y) continue;
                        float alpha = fminf(0.99f, o2.x * __expf(power));
                        if (alpha < (1.0f/255.0f)) continue;
                        float Tnew = Trun * (1.0f - alpha);
                        if (Tnew < 1e-4f) break;
                        float w = Trun * alpha;
                        cr += w * col.y;
                        cg += w * col.z;
                        cb += w * col.w;
                        Trun = Tnew;
                    }
                    done = true;
                }
            }
            if (__syncthreads_count(done ? 1 : 0) == NT) break;
        }
    }

    if (seg == 0) {
        int pxi = (ry0 + ty)*IMG_W + (rx0 + tx);
        out[0*IMG_H*IMG_W + pxi] = cr + bgr*Trun;
        out[1*IMG_H*IMG_W + pxi] = cg + bgg*Trun;
        out[2*IMG_H*IMG_W + pxi] = cb + bgb*Trun;
    }
}

// ---------------- launch ----------------
extern "C" void kernel_launch(void* const* d_in, const int* in_sizes, int n_in,
                              void* d_out, int out_size)
{
    const float* means3D   = (const float*)d_in[0];
    // d_in[1] = means2D (unused)
    const float* opacities = (const float*)d_in[2];
    const float* shs       = (const float*)d_in[3];
    const float* scales    = (const float*)d_in[4];
    const float* rotations = (const float*)d_in[5];
    const float* viewm     = (const float*)d_in[6];
    const float* projm     = (const float*)d_in[7];
    const float* campos    = (const float*)d_in[8];
    const float* bg        = (const float*)d_in[9];
    float* out = (float*)d_out;

    gauss_kernel<<<NBLK, NT>>>(means3D, opacities, shs, scales, rotations,
                               viewm, projm, campos, bg, out);
}